// round 5
// baseline (speedup 1.0000x reference)
#include <cuda_runtime.h>
#include <math.h>
#include <stdint.h>

#define T_TOK 16384
#define EMB   1024
#define NEXP  8
#define NSLOT (T_TOK * 2)

#define BM 128
#define BN 128
#define BK 32
#define NCH (EMB / BK)

#define STAGE_BYTES 32768      // A 16KB (rows 128B hi|lo swizzled) + B hi 8KB + B lo 8KB
#define SM_B_H 16384
#define NSTAGE 4
#define SMEM_BYTES (NSTAGE * STAGE_BYTES)

// ---------------- routing / scratch state ----------------
__device__ int   g_count[NEXP];
__device__ int   g_offset[NEXP];
__device__ int   g_cursor[NEXP];
__device__ int   g_tok_e[NSLOT];
__device__ float g_tok_w[NSLOT];
__device__ int   g_slot_token[NSLOT];
__device__ float g_slot_w[NSLOT];
// pre-converted operands (bf16 hi/lo pairs, 4B per element)
__device__ uint32_t g_xc[(size_t)T_TOK * EMB];        // x rows: per 32k-chunk [hi 64B | lo 64B]
__device__ uint32_t g_hc[(size_t)NSLOT * EMB];        // h rows: same layout
__device__ uint32_t g_w1c[(size_t)NEXP * EMB * EMB];  // [e][ntile][chunk][hi 8KB | lo 8KB]
__device__ uint32_t g_w2c[(size_t)NEXP * EMB * EMB];

// ---------------- PTX helpers (plain-sm_100-safe) ----------------
__device__ __forceinline__ uint32_t smem_u32(const void* p) {
    uint32_t a;
    asm("{ .reg .u64 t; cvta.to.shared.u64 t, %1; cvt.u32.u64 %0, t; }" : "=r"(a) : "l"(p));
    return a;
}
__device__ __forceinline__ void ldsm4(uint32_t* r, uint32_t addr) {
    asm volatile("ldmatrix.sync.aligned.m8n8.x4.shared.b16 {%0,%1,%2,%3}, [%4];"
                 : "=r"(r[0]), "=r"(r[1]), "=r"(r[2]), "=r"(r[3]) : "r"(addr));
}
__device__ __forceinline__ void ldsm4t(uint32_t* r, uint32_t addr) {
    asm volatile("ldmatrix.sync.aligned.m8n8.x4.trans.shared.b16 {%0,%1,%2,%3}, [%4];"
                 : "=r"(r[0]), "=r"(r[1]), "=r"(r[2]), "=r"(r[3]) : "r"(addr));
}
__device__ __forceinline__ void mma16816(float* d, const uint32_t* a, uint32_t b0, uint32_t b1) {
    asm volatile("mma.sync.aligned.m16n8k16.row.col.f32.bf16.bf16.f32 "
                 "{%0,%1,%2,%3}, {%4,%5,%6,%7}, {%8,%9}, {%0,%1,%2,%3};"
                 : "+f"(d[0]), "+f"(d[1]), "+f"(d[2]), "+f"(d[3])
                 : "r"(a[0]), "r"(a[1]), "r"(a[2]), "r"(a[3]), "r"(b0), "r"(b1));
}
__device__ __forceinline__ uint32_t packbf(float f0, float f1) {  // f0 -> low half
    uint32_t r;
    asm("cvt.rn.bf16x2.f32 %0, %1, %2;" : "=r"(r) : "f"(f1), "f"(f0));
    return r;
}
__device__ __forceinline__ void split4(const float4& v, uint2& hi, uint2& lo) {
    hi.x = packbf(v.x, v.y);
    hi.y = packbf(v.z, v.w);
    float hx = __uint_as_float(hi.x << 16), hy = __uint_as_float(hi.x & 0xffff0000u);
    float hz = __uint_as_float(hi.y << 16), hw = __uint_as_float(hi.y & 0xffff0000u);
    lo.x = packbf(v.x - hx, v.y - hy);
    lo.y = packbf(v.z - hz, v.w - hw);
}
__device__ __forceinline__ void cp16(uint32_t dst, const void* src) {
    asm volatile("cp.async.cg.shared.global [%0], [%1], 16;" :: "r"(dst), "l"(src) : "memory");
}
#define CP_COMMIT() asm volatile("cp.async.commit_group;" ::: "memory")
#define CP_WAIT2()  asm volatile("cp.async.wait_group 2;"  ::: "memory")

// ---------------- conversion kernels ----------------
__global__ __launch_bounds__(256) void conv_x_kernel(const float* __restrict__ x) {
    int idx = blockIdx.x * 256 + threadIdx.x;          // T_TOK * 256
    float4 v = ((const float4*)x)[idx];
    uint2 h, l; split4(v, h, l);
    int tok = idx >> 8, q = idx & 255;
    int c = q >> 3, j = q & 7;
    uint2* dst = (uint2*)g_xc;
    size_t b = (size_t)tok * 512 + c * 16 + j;
    dst[b] = h;  dst[b + 8] = l;
}

__global__ __launch_bounds__(256) void conv_w_kernel(const float* __restrict__ W,
                                                     uint32_t* __restrict__ dw) {
    int idx = blockIdx.x * 256 + threadIdx.x;          // NEXP * 1024 * 256
    float4 v = ((const float4*)W)[idx];
    uint2 h, l; split4(v, h, l);
    int e  = idx >> 18;
    int r  = idx & 0x3FFFF;
    int kk = r >> 8;            // global k 0..1023
    int n4 = r & 255;           // n/4 0..255
    int nt = n4 >> 5, nn4 = n4 & 31;
    int c  = kk >> 5, k = kk & 31;
    size_t b = (((size_t)(e * 8 + nt) * 32 + c) * 16384 + (size_t)k * 256 + nn4 * 8) >> 3;
    ((uint2*)dw)[b] = h;
    ((uint2*)dw)[b + 1024] = l;   // +8192 bytes
}

// ---------------- routing kernels ----------------
__global__ void reset_kernel() {
    int i = threadIdx.x;
    if (i < NEXP) { g_count[i] = 0; g_cursor[i] = 0; }
}

__global__ __launch_bounds__(256) void gate_kernel(const float* __restrict__ x,
                                                   const float* __restrict__ gw,
                                                   const float* __restrict__ gb) {
    __shared__ float sgw[EMB * NEXP];
    for (int i = threadIdx.x; i < EMB * NEXP; i += 256) sgw[i] = gw[i];
    __syncthreads();

    int warp = threadIdx.x >> 5, lane = threadIdx.x & 31;
    int t = blockIdx.x * 8 + warp;
    if (t >= T_TOK) return;

    const float* xr = x + (size_t)t * EMB;
    float acc[NEXP];
#pragma unroll
    for (int j = 0; j < NEXP; j++) acc[j] = 0.f;
    for (int d = lane; d < EMB; d += 32) {
        float xv = xr[d];
        const float* g = &sgw[d * NEXP];
#pragma unroll
        for (int j = 0; j < NEXP; j++) acc[j] += xv * g[j];
    }
#pragma unroll
    for (int off = 16; off; off >>= 1)
#pragma unroll
        for (int j = 0; j < NEXP; j++)
            acc[j] += __shfl_xor_sync(0xffffffffu, acc[j], off);

    if (lane == 0) {
        float l[NEXP];
        float mx = -1e30f;
#pragma unroll
        for (int j = 0; j < NEXP; j++) { l[j] = acc[j] + gb[j]; mx = fmaxf(mx, l[j]); }
        float s = 0.f;
#pragma unroll
        for (int j = 0; j < NEXP; j++) { l[j] = expf(l[j] - mx); s += l[j]; }
        float inv = 1.f / s;
#pragma unroll
        for (int j = 0; j < NEXP; j++) l[j] *= inv;

        int i0 = 0;
#pragma unroll
        for (int j = 1; j < NEXP; j++) if (l[j] > l[i0]) i0 = j;
        int i1 = (i0 == 0) ? 1 : 0;
#pragma unroll
        for (int j = 0; j < NEXP; j++) if (j != i0 && l[j] > l[i1]) i1 = j;

        float w0 = 1.f / (1.f + expf(l[i1] - l[i0]));   // softmax over top-2 probs
        g_tok_e[2 * t] = i0;  g_tok_e[2 * t + 1] = i1;
        g_tok_w[2 * t] = w0;  g_tok_w[2 * t + 1] = 1.f - w0;
        atomicAdd(&g_count[i0], 1);
        atomicAdd(&g_count[i1], 1);
    }
}

__global__ void scan_kernel() {
    if (threadIdx.x == 0) {
        int s = 0;
#pragma unroll
        for (int e = 0; e < NEXP; e++) { g_offset[e] = s; s += g_count[e]; }
    }
}

__global__ void scatter_kernel() {
    int i = blockIdx.x * 256 + threadIdx.x;
    if (i >= NSLOT) return;
    int e = g_tok_e[i];
    int pos = atomicAdd(&g_cursor[e], 1);
    int slot = g_offset[e] + pos;
    g_slot_token[slot] = i >> 1;
    g_slot_w[slot] = g_tok_w[i];
}

// ---------------- cp.async-pipelined bf16x3 grouped GEMM ----------------
// PASS 1: g_hc[slot] = split( relu(x[token] @ W1[e] + b1) )
// PASS 2: out[token] += w * (h[slot] @ W2[e] + b2)   (atomicAdd, 2 adds/elem)
template <int PASS>
__global__ __launch_bounds__(256, 1) void moe_mma(const uint32_t* __restrict__ Wc,
                                                  const float* __restrict__ Bias,
                                                  float* __restrict__ Out) {
    const int e     = blockIdx.z;
    const int cnt   = g_count[e];
    const int mbase = blockIdx.y * BM;
    if (mbase >= cnt) return;
    const int off = g_offset[e];
    const int n0  = blockIdx.x * BN;

    extern __shared__ char smem[];
    const uint32_t sb = smem_u32(smem);
    const int tid = threadIdx.x, lane = tid & 31, wid = tid >> 5;

    // ---- cp.async source/dest setup ----
    // A: thread covers row r = tid>>1, half (tid&1): 4 x 16B
    const int r  = tid >> 1;
    {   }
    int gm = mbase + r; if (gm > cnt - 1) gm = cnt - 1;
    const char* abase;
    if (PASS == 1) abase = (const char*)g_xc + (size_t)g_slot_token[off + gm] * 4096;
    else           abase = (const char*)g_hc + (size_t)(off + gm) * 4096;
    abase += (tid & 1) * 64;
    uint32_t adst[4];
#pragma unroll
    for (int i = 0; i < 4; i++) {
        int si = (tid & 1) * 4 + i;
        adst[i] = r * 128 + ((si ^ (r & 7)) << 4);
    }
    // B: thread copies 64B of the contiguous 16KB chunk block
    const char* bbase = (const char*)Wc + (size_t)(e * 8 + blockIdx.x) * 32 * 16384 + tid * 64;
    uint32_t bdst[4];
#pragma unroll
    for (int i = 0; i < 4; i++) {
        int o = tid * 64 + i * 16;
        int region = o >> 13;            // 0 = hi, 1 = lo
        int within = o & 8191;
        int k = within >> 8, c16 = (within >> 4) & 15;
        bdst[i] = SM_B_H + region * 8192 + k * 256 + ((c16 ^ (k & 7)) << 4);
    }

    auto load_stage = [&](int c, int s) {
        if (c < NCH) {
            uint32_t sa = sb + s * STAGE_BYTES;
            const char* ap = abase + c * 128;
#pragma unroll
            for (int i = 0; i < 4; i++) cp16(sa + adst[i], ap + i * 16);
            const char* bp = bbase + (size_t)c * 16384;
#pragma unroll
            for (int i = 0; i < 4; i++) cp16(sa + bdst[i], bp + i * 16);
        }
        CP_COMMIT();
    };

    // ---- ldmatrix per-lane offsets (unchanged layout) ----
    const int wm = (wid >> 2) * 64, wn = (wid & 3) * 32;
    uint32_t offAh[4][2], offAl[4][2], offB[2][2];
#pragma unroll
    for (int mt = 0; mt < 4; mt++) {
        int mrow = wm + mt * 16 + (lane & 15);
        int kc   = lane >> 4;
#pragma unroll
        for (int ks = 0; ks < 2; ks++) {
            int lc = ks * 2 + kc;
            offAh[mt][ks] = mrow * 128 + ((lc ^ (mrow & 7)) << 4);
            offAl[mt][ks] = mrow * 128 + (((lc + 4) ^ (mrow & 7)) << 4);
        }
    }
#pragma unroll
    for (int nt2 = 0; nt2 < 2; nt2++)
#pragma unroll
        for (int ks = 0; ks < 2; ks++) {
            int k  = ks * 16 + (lane & 7) + ((lane >> 3) & 1) * 8;
            int cn = (wid & 3) * 4 + nt2 * 2 + (lane >> 4);
            offB[nt2][ks] = k * 256 + ((cn ^ (k & 7)) << 4);
        }

    float acc[4][4][4];
#pragma unroll
    for (int a = 0; a < 4; a++)
#pragma unroll
        for (int b = 0; b < 4; b++)
#pragma unroll
            for (int c = 0; c < 4; c++) acc[a][b][c] = 0.f;

    auto compute = [&](int buf) {
        uint32_t ab = sb + buf * STAGE_BYTES;
        uint32_t bb = ab + SM_B_H;
#pragma unroll
        for (int ks = 0; ks < 2; ks++) {
            uint32_t Ah[4][4], Al[4][4], Bh[2][4], Bl[2][4];
#pragma unroll
            for (int mt = 0; mt < 4; mt++) {
                ldsm4(Ah[mt], ab + offAh[mt][ks]);
                ldsm4(Al[mt], ab + offAl[mt][ks]);
            }
#pragma unroll
            for (int nt2 = 0; nt2 < 2; nt2++) {
                ldsm4t(Bh[nt2], bb + offB[nt2][ks]);
                ldsm4t(Bl[nt2], bb + 8192 + offB[nt2][ks]);
            }
#pragma unroll
            for (int mt = 0; mt < 4; mt++)
#pragma unroll
                for (int nt = 0; nt < 4; nt++) {
                    const int q = nt >> 1, s = (nt & 1) * 2;
                    mma16816(acc[mt][nt], Ah[mt], Bh[q][s], Bh[q][s + 1]);
                    mma16816(acc[mt][nt], Ah[mt], Bl[q][s], Bl[q][s + 1]);
                    mma16816(acc[mt][nt], Al[mt], Bh[q][s], Bh[q][s + 1]);
                }
        }
    };

    load_stage(0, 0);
    load_stage(1, 1);
    load_stage(2, 2);
#pragma unroll 1
    for (int c = 0; c < NCH; c++) {
        CP_WAIT2();
        __syncthreads();
        compute(c & 3);
        load_stage(c + 3, (c + 3) & 3);
    }

    // ---- epilogue ----
    float bs[4][2];
#pragma unroll
    for (int nt = 0; nt < 4; nt++) {
        int col = n0 + wn + nt * 8 + (lane & 3) * 2;
        bs[nt][0] = Bias[(size_t)e * EMB + col];
        bs[nt][1] = Bias[(size_t)e * EMB + col + 1];
    }
    const int chunk = (n0 + wn) >> 5;   // this warp's 32 columns = one k-chunk of pass 2
#pragma unroll
    for (int mt = 0; mt < 4; mt++)
#pragma unroll
        for (int h = 0; h < 2; h++) {
            int m = mbase + wm + mt * 16 + (lane >> 2) + h * 8;
            if (m >= cnt) continue;
            if (PASS == 1) {
                uint32_t* hrow = g_hc + (size_t)(off + m) * 1024 + chunk * 32;
#pragma unroll
                for (int nt = 0; nt < 4; nt++) {
                    float v0 = fmaxf(acc[mt][nt][h * 2 + 0] + bs[nt][0], 0.f);
                    float v1 = fmaxf(acc[mt][nt][h * 2 + 1] + bs[nt][1], 0.f);
                    uint32_t hi = packbf(v0, v1);
                    float h0 = __uint_as_float(hi << 16);
                    float h1 = __uint_as_float(hi & 0xffff0000u);
                    uint32_t lo = packbf(v0 - h0, v1 - h1);
                    int colw = (nt * 8 + (lane & 3) * 2) >> 1;   // uint32 index within chunk
                    hrow[colw] = hi;
                    hrow[colw + 16] = lo;
                }
            } else {
                int   tok = g_slot_token[off + m];
                float wgt = g_slot_w[off + m];
                float* orow = Out + (size_t)tok * EMB + n0 + wn;
#pragma unroll
                for (int nt = 0; nt < 4; nt++) {
                    int col = nt * 8 + (lane & 3) * 2;
                    atomicAdd(orow + col,     wgt * (acc[mt][nt][h * 2 + 0] + bs[nt][0]));
                    atomicAdd(orow + col + 1, wgt * (acc[mt][nt][h * 2 + 1] + bs[nt][1]));
                }
            }
        }
}

extern "C" void kernel_launch(void* const* d_in, const int* in_sizes, int n_in,
                              void* d_out, int out_size) {
    const float* x  = (const float*)d_in[0];
    const float* gw = (const float*)d_in[1];
    const float* gb = (const float*)d_in[2];
    const float* W1 = (const float*)d_in[3];
    const float* b1 = (const float*)d_in[4];
    const float* W2 = (const float*)d_in[5];
    const float* b2 = (const float*)d_in[6];
    float* out = (float*)d_out;

    cudaFuncSetAttribute(moe_mma<1>, cudaFuncAttributeMaxDynamicSharedMemorySize, SMEM_BYTES);
    cudaFuncSetAttribute(moe_mma<2>, cudaFuncAttributeMaxDynamicSharedMemorySize, SMEM_BYTES);

    cudaMemsetAsync(out, 0, (size_t)out_size * sizeof(float));
    reset_kernel<<<1, 32>>>();
    conv_x_kernel<<<T_TOK, 256>>>(x);
    {
        uint32_t* w1c; cudaGetSymbolAddress((void**)&w1c, g_w1c);
        uint32_t* w2c; cudaGetSymbolAddress((void**)&w2c, g_w2c);
        conv_w_kernel<<<NEXP * 1024, 256>>>(W1, w1c);
        conv_w_kernel<<<NEXP * 1024, 256>>>(W2, w2c);
    }
    gate_kernel<<<T_TOK / 8, 256>>>(x, gw, gb);
    scan_kernel<<<1, 1>>>();
    scatter_kernel<<<NSLOT / 256, 256>>>();

    uint32_t* w1c; cudaGetSymbolAddress((void**)&w1c, g_w1c);
    uint32_t* w2c; cudaGetSymbolAddress((void**)&w2c, g_w2c);
    dim3 grid(EMB / BN, NSLOT / BM, NEXP);
    moe_mma<1><<<grid, 256, SMEM_BYTES>>>(w1c, b1, nullptr);
    moe_mma<2><<<grid, 256, SMEM_BYTES>>>(w2c, b2, out);
}